// round 9
// baseline (speedup 1.0000x reference)
#include <cuda_runtime.h>
#include <cuda_fp16.h>
#include <cstdint>

#define N_NODES 300000
#define N_EDGES 600000
#define N_GRAPHS 12000
#define HID 128
#define F_ATOM 9
#define V_ATOM 119
#define D_ATOM 9
#define EMB_SZ (F_ATOM * V_ATOM * D_ATOM)   // 9639 floats

#define SCAN_E 1024
#define NSB ((N_NODES + SCAN_E - 1) / SCAN_E)   // 293

// ---------------- scratch (device globals; no allocations allowed) ----------
__device__ __half g_h1h[(size_t)N_NODES * HID];   // h1 (fp16)
__device__ __half g_a1h[(size_t)N_NODES * HID];   // relu(agg1) (fp16)
__device__ int    g_deg[N_NODES];
__device__ float  g_dinv[N_NODES];
__device__ int    g_rowptr[N_NODES + 1];
__device__ int    g_fill[N_NODES];
__device__ uint2  g_csre[N_EDGES];                // (src, coef-bits)
__device__ int    g_bsum[NSB];
__device__ float  g_cnt[N_GRAPHS];
__device__ float  g_pool[N_GRAPHS * HID];
__device__ float  g_wc[HID * HID];
__device__ float  g_bc[HID];

// ---------------- degree (edges only; dst via int4) -------------------------
__global__ void k_deg(const int* __restrict__ ei) {
    int i = blockIdx.x * blockDim.x + threadIdx.x;
    int stride = gridDim.x * blockDim.x;
    const int NV = N_EDGES / 4;
    const int4* dst4 = (const int4*)(ei + N_EDGES);
    for (int j = i; j < NV; j += stride) {
        int4 d = __ldg(&dst4[j]);
        atomicAdd(&g_deg[d.x], 1);
        atomicAdd(&g_deg[d.y], 1);
        atomicAdd(&g_deg[d.z], 1);
        atomicAdd(&g_deg[d.w], 1);
    }
}

// ---------------- per-graph node counts (stream A) ---------------------------
__global__ void k_cnt(const int* __restrict__ batch) {
    int i = blockIdx.x * blockDim.x + threadIdx.x;
    int stride = gridDim.x * blockDim.x;
    for (int n = i; n < N_NODES; n += stride)
        atomicAdd(&g_cnt[batch[n]], 1.f);
}

// ---------------- scan part 1 ------------------------------------------------
__global__ void k_scan1() {
    __shared__ int s[256];
    int t = threadIdx.x;
    int base = blockIdx.x * SCAN_E + t * 4;
    int v[4];
#pragma unroll
    for (int k = 0; k < 4; k++) v[k] = (base + k < N_NODES) ? g_deg[base + k] : 0;
    v[1] += v[0]; v[2] += v[1]; v[3] += v[2];
    s[t] = v[3];
    __syncthreads();
    for (int off = 1; off < 256; off <<= 1) {
        int add = (t >= off) ? s[t - off] : 0;
        __syncthreads();
        s[t] += add;
        __syncthreads();
    }
    int pre = (t > 0) ? s[t - 1] : 0;
#pragma unroll
    for (int k = 0; k < 4; k++)
        if (base + k < N_NODES) g_rowptr[base + k + 1] = v[k] + pre;
    if (t == 255) g_bsum[blockIdx.x] = s[255];
}

// ---------------- scan parts 2+3 fused ---------------------------------------
__global__ void __launch_bounds__(512) k_scan23() {
    __shared__ int s[512];
    int t = threadIdx.x;
    s[t] = (t < NSB) ? g_bsum[t] : 0;
    __syncthreads();
    for (int off = 1; off < 512; off <<= 1) {
        int v = (t >= off) ? s[t - off] : 0;
        __syncthreads();
        s[t] += v;
        __syncthreads();
    }
    int i = blockIdx.x * 512 + t;
    if (i >= N_NODES) return;
    int blk = i / SCAN_E;
    int add = (blk > 0) ? s[blk - 1] : 0;
    int incl = g_rowptr[i + 1] + add;
    g_rowptr[i + 1] = incl;
    int d = g_deg[i];
    g_fill[i] = incl - d;
    g_dinv[i] = rsqrtf((float)d + 1.0f);
    if (i == 0) g_rowptr[0] = 0;
}

// ---------------- scatter edges into CSR with precomputed coef ---------------
__global__ void k_scatter(const int* __restrict__ ei) {
    int e = blockIdx.x * blockDim.x + threadIdx.x;
    if (e >= N_EDGES) return;
    int src = __ldg(&ei[e]);
    int dst = __ldg(&ei[N_EDGES + e]);
    float c = __ldg(&g_dinv[src]) * __ldg(&g_dinv[dst]);
    int pos = atomicAdd(&g_fill[dst], 1);
    g_csre[pos] = make_uint2((unsigned)src, __float_as_uint(c));
}

// ---------------- embed + h1 = h0@W1 (fp16 out) ------------------------------
__global__ void __launch_bounds__(256) k_embed(const int* __restrict__ x,
                                               const float* __restrict__ emb,
                                               const float* __restrict__ W1) {
    __shared__ float s_emb[EMB_SZ];
    __shared__ float s_h0[8][16];
    int tid = threadIdx.x;
    for (int i = tid; i < EMB_SZ; i += 256) s_emb[i] = emb[i];

    int warp = tid >> 5, lane = tid & 31;
    float4 w[D_ATOM];
    const float4* W1v = (const float4*)W1;
#pragma unroll
    for (int d = 0; d < D_ATOM; d++) w[d] = W1v[d * (HID / 4) + lane];
    __syncthreads();

    int gwarp = blockIdx.x * 8 + warp;
    const int NW = 592 * 8;
    for (int n = gwarp; n < N_NODES; n += NW) {
        int xv = 0;
        if (lane < F_ATOM) xv = __ldg(&x[n * F_ATOM + lane]);
        int xf[F_ATOM];
#pragma unroll
        for (int f = 0; f < F_ATOM; f++) xf[f] = __shfl_sync(0xffffffffu, xv, f);

        if (lane < D_ATOM) {
            float h = 0.f;
#pragma unroll
            for (int f = 0; f < F_ATOM; f++)
                h += s_emb[(f * V_ATOM + xf[f]) * D_ATOM + lane];
            s_h0[warp][lane] = h;
        }
        __syncwarp();
        float4 acc = make_float4(0.f, 0.f, 0.f, 0.f);
#pragma unroll
        for (int d = 0; d < D_ATOM; d++) {
            float h = s_h0[warp][d];
            acc.x += h * w[d].x; acc.y += h * w[d].y;
            acc.z += h * w[d].z; acc.w += h * w[d].w;
        }
        __syncwarp();

        __half2 p0 = __floats2half2_rn(acc.x, acc.y);
        __half2 p1 = __floats2half2_rn(acc.z, acc.w);
        uint2 u;
        u.x = *reinterpret_cast<unsigned*>(&p0);
        u.y = *reinterpret_cast<unsigned*>(&p1);
        ((uint2*)(g_h1h + (size_t)n * HID))[lane] = u;
    }
}

// ---------------- helpers ----------------------------------------------------
struct F8 { float v[8]; };

__device__ __forceinline__ F8 unpack_h8(uint4 u) {
    F8 r;
    float2 a = __half22float2(*reinterpret_cast<__half2*>(&u.x));
    float2 b = __half22float2(*reinterpret_cast<__half2*>(&u.y));
    float2 c = __half22float2(*reinterpret_cast<__half2*>(&u.z));
    float2 d = __half22float2(*reinterpret_cast<__half2*>(&u.w));
    r.v[0] = a.x; r.v[1] = a.y; r.v[2] = b.x; r.v[3] = b.y;
    r.v[4] = c.x; r.v[5] = c.y; r.v[6] = d.x; r.v[7] = d.y;
    return r;
}

__device__ __forceinline__ uint4 pack_h8(const float* a) {
    __half2 p0 = __floats2half2_rn(a[0], a[1]);
    __half2 p1 = __floats2half2_rn(a[2], a[3]);
    __half2 p2 = __floats2half2_rn(a[4], a[5]);
    __half2 p3 = __floats2half2_rn(a[6], a[7]);
    uint4 u;
    u.x = *reinterpret_cast<unsigned*>(&p0);
    u.y = *reinterpret_cast<unsigned*>(&p1);
    u.z = *reinterpret_cast<unsigned*>(&p2);
    u.w = *reinterpret_cast<unsigned*>(&p3);
    return u;
}

// ---------------- pass1: relu(agg1) = relu(Â h1 + b1) -> g_a1h ---------------
// Half-warp (16 lanes x uint4) per node.
__global__ void __launch_bounds__(256) k_pass1(const float* __restrict__ b1) {
    int n = blockIdx.x * 16 + (threadIdx.x >> 4);
    if (n >= N_NODES) return;
    int lane = threadIdx.x & 15;

    int r0 = __ldg(&g_rowptr[n]);
    int r1 = __ldg(&g_rowptr[n + 1]);
    float dn = __ldg(&g_dinv[n]);
    float s = dn * dn;

    uint4 u = __ldg(((const uint4*)(g_h1h + (size_t)n * HID)) + lane);
    F8 v = unpack_h8(u);
    float4 bb0 = __ldg(((const float4*)b1) + lane * 2);
    float4 bb1 = __ldg(((const float4*)b1) + lane * 2 + 1);
    float acc[8];
    acc[0] = v.v[0] * s + bb0.x; acc[1] = v.v[1] * s + bb0.y;
    acc[2] = v.v[2] * s + bb0.z; acc[3] = v.v[3] * s + bb0.w;
    acc[4] = v.v[4] * s + bb1.x; acc[5] = v.v[5] * s + bb1.y;
    acc[6] = v.v[6] * s + bb1.z; acc[7] = v.v[7] * s + bb1.w;

    uint2 en = (r0 < r1) ? __ldg(&g_csre[r0]) : make_uint2(0u, 0u);
    for (int j = r0; j < r1; j++) {
        uint2 e = en;
        if (j + 1 < r1) en = __ldg(&g_csre[j + 1]);
        float c = __uint_as_float(e.y);
        uint4 us = __ldg(((const uint4*)(g_h1h + (size_t)e.x * HID)) + lane);
        F8 vs = unpack_h8(us);
#pragma unroll
        for (int k = 0; k < 8; k++) acc[k] += vs.v[k] * c;
    }

#pragma unroll
    for (int k = 0; k < 8; k++) acc[k] = fmaxf(acc[k], 0.f);
    uint4 uo = pack_h8(acc);
    uint4* op = ((uint4*)(g_a1h + (size_t)n * HID)) + lane;
    asm volatile("st.global.cs.v4.u32 [%0], {%1,%2,%3,%4};"
                 :: "l"(op), "r"(uo.x), "r"(uo.y), "r"(uo.z), "r"(uo.w)
                 : "memory");
}

// ---------------- pass2 fused with pooling -----------------------------------
__global__ void __launch_bounds__(256) k_pass2(const int* __restrict__ batch) {
    int n = blockIdx.x * 16 + (threadIdx.x >> 4);
    if (n >= N_NODES) return;
    int lane = threadIdx.x & 15;

    int r0 = __ldg(&g_rowptr[n]);
    int r1 = __ldg(&g_rowptr[n + 1]);
    float dn = __ldg(&g_dinv[n]);
    float s = dn * dn;
    int g = __ldg(&batch[n]);

    uint4 u = __ldg(((const uint4*)(g_a1h + (size_t)n * HID)) + lane);
    F8 v = unpack_h8(u);
    float acc[8];
#pragma unroll
    for (int k = 0; k < 8; k++) acc[k] = v.v[k] * s;

    uint2 en = (r0 < r1) ? __ldg(&g_csre[r0]) : make_uint2(0u, 0u);
    for (int j = r0; j < r1; j++) {
        uint2 e = en;
        if (j + 1 < r1) en = __ldg(&g_csre[j + 1]);
        float c = __uint_as_float(e.y);
        uint4 us = __ldg(((const uint4*)(g_a1h + (size_t)e.x * HID)) + lane);
        F8 vs = unpack_h8(us);
#pragma unroll
        for (int k = 0; k < 8; k++) acc[k] += vs.v[k] * c;
    }

    float* pp = g_pool + (size_t)g * HID + lane * 8;
    asm volatile("red.global.add.v4.f32 [%0], {%1,%2,%3,%4};"
                 :: "l"(pp), "f"(acc[0]), "f"(acc[1]), "f"(acc[2]), "f"(acc[3])
                 : "memory");
    asm volatile("red.global.add.v4.f32 [%0], {%1,%2,%3,%4};"
                 :: "l"(pp + 4), "f"(acc[4]), "f"(acc[5]), "f"(acc[6]), "f"(acc[7])
                 : "memory");
}

// ---------------- Wc = W2 @ Wfc ; Bc = b2 @ Wfc + bfc -----------------------
__global__ void k_wc(const float* __restrict__ W2, const float* __restrict__ Wfc,
                     const float* __restrict__ b2, const float* __restrict__ bfc) {
    int i = blockIdx.x;
    int j = threadIdx.x;
    float acc = 0.f;
    for (int k = 0; k < HID; k++) acc += W2[i * HID + k] * Wfc[k * HID + j];
    g_wc[i * HID + j] = acc;
    if (i == 0) {
        float a = bfc[j];
        for (int k = 0; k < HID; k++) a += b2[k] * Wfc[k * HID + j];
        g_bc[j] = a;
    }
}

// ---------------- final: out = (pool/cnt) @ Wc + Bc -------------------------
__global__ void k_out(float* __restrict__ out) {
    __shared__ float p[HID];
    int g = blockIdx.x;
    int c = threadIdx.x;
    float cnt = fmaxf(g_cnt[g], 1.f);
    p[c] = g_pool[g * HID + c] / cnt;
    __syncthreads();
    float acc = g_bc[c];
#pragma unroll 8
    for (int k = 0; k < HID; k++) acc += p[k] * g_wc[k * HID + c];
    out[g * HID + c] = acc;
}

// ---------------- launch: fork-join two-stream graph -------------------------
extern "C" void kernel_launch(void* const* d_in, const int* in_sizes, int n_in,
                              void* d_out, int out_size) {
    const int*   x     = (const int*)d_in[0];
    const int*   ei    = (const int*)d_in[1];
    const int*   batch = (const int*)d_in[3];
    const float* aemb  = (const float*)d_in[4];
    const float* W1    = (const float*)d_in[6];
    const float* b1    = (const float*)d_in[7];
    const float* W2    = (const float*)d_in[8];
    const float* b2    = (const float*)d_in[9];
    const float* Wfc   = (const float*)d_in[10];
    const float* bfc   = (const float*)d_in[11];
    float* out = (float*)d_out;

    static cudaStream_t sA = nullptr, sB = nullptr;
    static cudaEvent_t eF = nullptr, eA = nullptr, eB = nullptr;
    static void *p_deg = nullptr, *p_pool = nullptr, *p_cnt = nullptr;
    if (sA == nullptr) {
        cudaStreamCreateWithFlags(&sA, cudaStreamNonBlocking);
        cudaStreamCreateWithFlags(&sB, cudaStreamNonBlocking);
        cudaEventCreateWithFlags(&eF, cudaEventDisableTiming);
        cudaEventCreateWithFlags(&eA, cudaEventDisableTiming);
        cudaEventCreateWithFlags(&eB, cudaEventDisableTiming);
        cudaGetSymbolAddress(&p_deg, g_deg);
        cudaGetSymbolAddress(&p_pool, g_pool);
        cudaGetSymbolAddress(&p_cnt, g_cnt);
    }

    // fork from the (captured) base stream
    cudaEventRecord(eF, 0);
    cudaStreamWaitEvent(sA, eF, 0);
    cudaStreamWaitEvent(sB, eF, 0);

    // stream A: pool/cnt zero + batch counts + embedding + weight precompute
    cudaMemsetAsync(p_pool, 0, (size_t)N_GRAPHS * HID * sizeof(float), sA);
    cudaMemsetAsync(p_cnt, 0, (size_t)N_GRAPHS * sizeof(float), sA);
    k_cnt<<<1024, 256, 0, sA>>>(batch);
    k_embed<<<592, 256, 0, sA>>>(x, aemb, W1);
    k_wc<<<HID, HID, 0, sA>>>(W2, Wfc, b2, bfc);

    // stream B: CSR build chain
    cudaMemsetAsync(p_deg, 0, (size_t)N_NODES * sizeof(int), sB);
    k_deg<<<586, 256, 0, sB>>>(ei);
    k_scan1<<<NSB, 256, 0, sB>>>();
    k_scan23<<<(N_NODES + 511) / 512, 512, 0, sB>>>();
    k_scatter<<<(N_EDGES + 255) / 256, 256, 0, sB>>>(ei);

    // join back to base stream
    cudaEventRecord(eA, sA);
    cudaEventRecord(eB, sB);
    cudaStreamWaitEvent(0, eA, 0);
    cudaStreamWaitEvent(0, eB, 0);

    k_pass1<<<(N_NODES + 15) / 16, 256>>>(b1);
    k_pass2<<<(N_NODES + 15) / 16, 256>>>(batch);
    k_out<<<N_GRAPHS, HID>>>(out);
}